// round 1
// baseline (speedup 1.0000x reference)
#include <cuda_runtime.h>

#define NS   16
#define SS   32
#define ENCD 64
#define HIDD 128
#define OUTD 8
#define WPB  8
#define THREADS (WPB * 32)

// Shared layout (floats):
//   sWf  [HIDD*HIDD]  = 16384
//   sWd  [HIDD*OUTD]  = 1024
//   sbf  [HIDD]       = 128
//   sbd  [OUTD]       = 8
//   swe  [SS*ENCD]    = 2048   (staging for reg preload)
//   per-warp: st[NS*SS]=512, fin[HIDD]=128, hid[HIDD]=128  -> 768 * WPB
#define SMEM_FLOATS (HIDD*HIDD + HIDD*OUTD + HIDD + OUTD + SS*ENCD + WPB*(NS*SS + HIDD + HIDD))

__global__ __launch_bounds__(THREADS, 2)
void gnn_kernel(const float* __restrict__ obs,
                const float* __restrict__ We, const float* __restrict__ be,
                const float* __restrict__ Wf, const float* __restrict__ bf,
                const float* __restrict__ Wd, const float* __restrict__ bd,
                float* __restrict__ out, int B)
{
    extern __shared__ float sm[];
    float* sWf = sm;                         // 16384
    float* sWd = sWf + HIDD * HIDD;          // 1024
    float* sbf = sWd + HIDD * OUTD;          // 128
    float* sbd = sbf + HIDD;                 // 8
    float* swe = sbd + OUTD;                 // 2048
    float* warpbase = swe + SS * ENCD;

    const int tid  = threadIdx.x;
    const int lane = tid & 31;
    const int warp = tid >> 5;

    // Stage weights into shared
    for (int i = tid; i < HIDD * HIDD; i += THREADS) sWf[i] = Wf[i];
    for (int i = tid; i < HIDD * OUTD; i += THREADS) sWd[i] = Wd[i];
    for (int i = tid; i < SS * ENCD;   i += THREADS) swe[i] = We[i];
    if (tid < HIDD) sbf[tid] = bf[tid];
    if (tid < OUTD) sbd[tid] = bd[tid];
    __syncthreads();

    // Preload W_enc columns (lane, lane+32) into registers: 64 regs/lane
    float wel[SS], weh[SS];
#pragma unroll
    for (int s = 0; s < SS; s++) {
        wel[s] = swe[s * ENCD + lane];
        weh[s] = swe[s * ENCD + lane + 32];
    }
    const float be0 = be[lane];
    const float be1 = be[lane + 32];

    float* st  = warpbase + warp * (NS * SS + HIDD + HIDD);
    float* fin = st + NS * SS;
    float* hid = fin + HIDD;

    const int gw = blockIdx.x * WPB + warp;
    const int nw = gridDim.x * WPB;

    for (int b = gw; b < B; b += nw) {
        // ---- load states (512 floats) into per-warp shared
        const float4* src = (const float4*)(obs + (size_t)b * (NS * SS));
        float4* dst = (float4*)st;
#pragma unroll
        for (int i = 0; i < 4; i++) dst[lane + 32 * i] = src[lane + 32 * i];
        __syncwarp();

        // ---- encoder + masked-mean aggregation
        float g0, g1, a0 = 0.f, a1 = 0.f, run = 1.f, cnt = 0.f;
        {
            const float* stn = st;
            float acc0 = be0, acc1 = be1;
#pragma unroll
            for (int s = 0; s < SS; s++) {
                float v = stn[s];
                acc0 = fmaf(v, wel[s], acc0);
                acc1 = fmaf(v, weh[s], acc1);
            }
            g0 = fmaxf(acc0, 0.f);
            g1 = fmaxf(acc1, 0.f);
        }
#pragma unroll 5
        for (int n = 1; n < NS; n++) {
            const float* stn = st + n * SS;
            float acc0 = be0, acc1 = be1;
#pragma unroll
            for (int s = 0; s < SS; s++) {
                float v = stn[s];
                acc0 = fmaf(v, wel[s], acc0);
                acc1 = fmaf(v, weh[s], acc1);
            }
            run = (stn[0] == 1.0f) ? run : 0.f;   // cumprod of (flag == 1)
            cnt += run;
            a0 = fmaf(run, fmaxf(acc0, 0.f), a0);
            a1 = fmaf(run, fmaxf(acc1, 0.f), a1);
        }
        float m = fmaxf(cnt, 1.f);
        a0 = a0 / m;
        a1 = a1 / m;

        fin[lane]      = g0;
        fin[lane + 32] = g1;
        fin[lane + 64] = a0;
        fin[lane + 96] = a1;
        __syncwarp();

        // ---- hidden = relu(f_in @ W_f + b_f); each lane owns 4 h-columns
        float h0 = sbf[lane], h1 = sbf[lane + 32], h2 = sbf[lane + 64], h3 = sbf[lane + 96];
#pragma unroll 16
        for (int k = 0; k < HIDD; k++) {
            float v = fin[k];
            const float* row = sWf + k * HIDD;
            h0 = fmaf(v, row[lane],      h0);
            h1 = fmaf(v, row[lane + 32], h1);
            h2 = fmaf(v, row[lane + 64], h2);
            h3 = fmaf(v, row[lane + 96], h3);
        }
        hid[lane]      = fmaxf(h0, 0.f);
        hid[lane + 32] = fmaxf(h1, 0.f);
        hid[lane + 64] = fmaxf(h2, 0.f);
        hid[lane + 96] = fmaxf(h3, 0.f);
        __syncwarp();

        // ---- logits = hidden @ W_dec + b_dec (4-way split + shuffle reduce)
        const int o = lane & 7, q = lane >> 3;
        float p = 0.f;
        const float* hq = hid + q * 32;
        const float* wq = sWd + q * 32 * OUTD + o;
#pragma unroll
        for (int h = 0; h < 32; h++) p = fmaf(hq[h], wq[h * OUTD], p);
        p += __shfl_down_sync(0xffffffffu, p, 16);
        p += __shfl_down_sync(0xffffffffu, p, 8);
        if (lane < 8) out[(size_t)b * OUTD + lane] = p + sbd[lane];
        __syncwarp();
    }
}

extern "C" void kernel_launch(void* const* d_in, const int* in_sizes, int n_in,
                              void* d_out, int out_size)
{
    const float* obs = (const float*)d_in[0];
    const float* We  = (const float*)d_in[1];
    const float* be  = (const float*)d_in[2];
    const float* Wf  = (const float*)d_in[3];
    const float* bf  = (const float*)d_in[4];
    const float* Wd  = (const float*)d_in[5];
    const float* bd  = (const float*)d_in[6];
    float* out = (float*)d_out;

    const int B = in_sizes[0] / (NS * SS);
    const size_t smem = SMEM_FLOATS * sizeof(float);

    static int attr_done = 0;
    cudaFuncSetAttribute(gnn_kernel, cudaFuncAttributeMaxDynamicSharedMemorySize, (int)smem);
    (void)attr_done;

    const int blocks = 304;  // ~2 per SM, grid-stride over B
    gnn_kernel<<<blocks, THREADS, smem>>>(obs, We, be, Wf, bf, Wd, bd, out, B);
}

// round 3
// speedup vs baseline: 1.7869x; 1.7869x over previous
#include <cuda_runtime.h>

#define NS   16
#define SS   32
#define ENCD 64
#define HIDD 128
#define OUTD 8
#define WPB  8
#define THREADS (WPB * 32)
#define EPW  4     // elements per warp per iteration (B=32768 divisible by 4)

typedef unsigned long long u64;

__device__ __forceinline__ u64 fma2(u64 a, u64 b, u64 c) {
    u64 d;
    asm("fma.rn.f32x2 %0, %1, %2, %3;" : "=l"(d) : "l"(a), "l"(b), "l"(c));
    return d;
}
__device__ __forceinline__ float lo_f(u64 v) { return __uint_as_float((unsigned)v); }
__device__ __forceinline__ float hi_f(u64 v) { return __uint_as_float((unsigned)(v >> 32)); }
__device__ __forceinline__ float sum2(u64 v) { return lo_f(v) + hi_f(v); }

// Shared layout (floats):
//   sWfT4 [32*128*4 = 16384]  : float4 (Wf[4k2][c],Wf[4k2+1][c],Wf[4k2+2][c],Wf[4k2+3][c])
//   sWdT  [64*8*2   = 1024]   : float2 (Wd[2h][o], Wd[2h+1][o])
//   sWeP  [16*64*2  = 2048]   : float2 (We[2j][c], We[2j+1][c])
//   sbf[128] sbd[8] sbe[64]
//   per-warp: fin[EPW*128] + hid[128] = 640  -> * WPB
#define SMEM_FLOATS (16384 + 1024 + 2048 + 128 + 8 + 64 + WPB * (EPW * HIDD + HIDD))

__global__ __launch_bounds__(THREADS, 2)
void gnn_kernel(const float* __restrict__ obs,
                const float* __restrict__ We, const float* __restrict__ be,
                const float* __restrict__ Wf, const float* __restrict__ bf,
                const float* __restrict__ Wd, const float* __restrict__ bd,
                float* __restrict__ out, int B)
{
    extern __shared__ float sm[];
    float* sWfT4 = sm;                 // 16384
    float* sWdT  = sWfT4 + 16384;      // 1024
    float* sWeP  = sWdT + 1024;        // 2048
    float* sbf   = sWeP + 2048;        // 128
    float* sbd   = sbf + 128;          // 8
    float* sbe   = sbd + 8;            // 64
    float* warpf = sbe + 64;           // per-warp region (16B aligned: offset 19656*4 bytes)

    const int tid  = threadIdx.x;
    const int lane = tid & 31;
    const int warp = tid >> 5;

    // ---- stage transposed/paired weights into shared
    for (int i = tid; i < 32 * HIDD; i += THREADS) {
        int k2 = i >> 7, c = i & 127;
        const float* wp = Wf + (4 * k2) * HIDD + c;
        ((float4*)sWfT4)[i] = make_float4(wp[0], wp[HIDD], wp[2 * HIDD], wp[3 * HIDD]);
    }
    for (int i = tid; i < 64 * OUTD; i += THREADS) {
        int hp = i >> 3, o = i & 7;
        ((float2*)sWdT)[i] = make_float2(Wd[2 * hp * OUTD + o], Wd[(2 * hp + 1) * OUTD + o]);
    }
    for (int i = tid; i < 16 * ENCD; i += THREADS) {
        int j = i >> 6, c = i & 63;
        ((float2*)sWeP)[i] = make_float2(We[2 * j * ENCD + c], We[(2 * j + 1) * ENCD + c]);
    }
    if (tid < HIDD) sbf[tid] = bf[tid];
    if (tid < OUTD) sbd[tid] = bd[tid];
    if (tid < ENCD) sbe[tid] = be[tid];
    __syncthreads();

    // ---- per-lane register preload: encoder weight pairs for col = lane
    const u64* sWeU = (const u64*)sWeP;
    u64 w0r[16];
#pragma unroll
    for (int j = 0; j < 16; j++) w0r[j] = sWeU[j * 64 + lane];
    const float be0 = sbe[lane];
    const float be1 = sbe[lane + 32];

    float* fin = warpf + warp * (EPW * HIDD + HIDD);
    float* hid = fin + EPW * HIDD;

    const int gw = blockIdx.x * WPB + warp;
    const int nw = gridDim.x * WPB;

    for (int b0 = gw * EPW; b0 < B; b0 += nw * EPW) {
        // ================= encoder + masked mean, per element =================
#pragma unroll 1
        for (int e = 0; e < EPW; e++) {
            const int b = b0 + e;
            const ulonglong2* rp = (const ulonglong2*)(obs + (size_t)b * (NS * SS));

            // agent (n = 0)
            u64 a0 = 0, a1 = 0;
            {
                ulonglong2 rr[8];
#pragma unroll
                for (int i = 0; i < 8; i++) rr[i] = __ldg(rp + i);
#pragma unroll
                for (int i = 0; i < 8; i++) {
                    a0 = fma2(w0r[2 * i],     rr[i].x, a0);
                    a0 = fma2(w0r[2 * i + 1], rr[i].y, a0);
                    a1 = fma2(sWeU[(2 * i) * 64 + lane + 32],     rr[i].x, a1);
                    a1 = fma2(sWeU[(2 * i + 1) * 64 + lane + 32], rr[i].y, a1);
                }
            }
            const float g0 = fmaxf(sum2(a0) + be0, 0.f);
            const float g1 = fmaxf(sum2(a1) + be1, 0.f);

            // neighbors: cumprod mask -> early exit at first invalid flag
            float s0 = 0.f, s1 = 0.f, cnt = 0.f;
            for (int n = 1; n < NS; n++) {
                const ulonglong2* rn = rp + n * 8;
                ulonglong2 rr0 = __ldg(rn);
                if (lo_f(rr0.x) != 1.0f) break;   // warp-uniform branch
                cnt += 1.f;
                ulonglong2 rr[8];
                rr[0] = rr0;
#pragma unroll
                for (int i = 1; i < 8; i++) rr[i] = __ldg(rn + i);
                u64 c0 = 0, c1 = 0;
#pragma unroll
                for (int i = 0; i < 8; i++) {
                    c0 = fma2(w0r[2 * i],     rr[i].x, c0);
                    c0 = fma2(w0r[2 * i + 1], rr[i].y, c0);
                    c1 = fma2(sWeU[(2 * i) * 64 + lane + 32],     rr[i].x, c1);
                    c1 = fma2(sWeU[(2 * i + 1) * 64 + lane + 32], rr[i].y, c1);
                }
                s0 += fmaxf(sum2(c0) + be0, 0.f);
                s1 += fmaxf(sum2(c1) + be1, 0.f);
            }
            const float inv = 1.0f / fmaxf(cnt, 1.f);
            fin[e * HIDD + lane]      = g0;
            fin[e * HIDD + lane + 32] = g1;
            fin[e * HIDD + lane + 64] = s0 * inv;
            fin[e * HIDD + lane + 96] = s1 * inv;
        }
        __syncwarp();

        // ================= hidden GEMM: 4 elements share W_f reads =================
        u64 acc[EPW][4];
#pragma unroll
        for (int e = 0; e < EPW; e++)
#pragma unroll
            for (int c = 0; c < 4; c++) acc[e][c] = 0ull;

        const ulonglong2* WT = (const ulonglong2*)sWfT4;   // [k2*128 + c]
        const ulonglong2* fU = (const ulonglong2*)fin;     // [e*32 + k2]
#pragma unroll 4
        for (int k2 = 0; k2 < 32; k2++) {
            const ulonglong2 w0 = WT[k2 * 128 + lane];
            const ulonglong2 w1 = WT[k2 * 128 + lane + 32];
            const ulonglong2 w2 = WT[k2 * 128 + lane + 64];
            const ulonglong2 w3 = WT[k2 * 128 + lane + 96];
#pragma unroll
            for (int e = 0; e < EPW; e++) {
                const ulonglong2 f = fU[e * 32 + k2];
                acc[e][0] = fma2(w0.x, f.x, acc[e][0]);
                acc[e][0] = fma2(w0.y, f.y, acc[e][0]);
                acc[e][1] = fma2(w1.x, f.x, acc[e][1]);
                acc[e][1] = fma2(w1.y, f.y, acc[e][1]);
                acc[e][2] = fma2(w2.x, f.x, acc[e][2]);
                acc[e][2] = fma2(w2.y, f.y, acc[e][2]);
                acc[e][3] = fma2(w3.x, f.x, acc[e][3]);
                acc[e][3] = fma2(w3.y, f.y, acc[e][3]);
            }
        }

        // ================= epilogue + decode, per element =================
        const int o = lane & 7, q = lane >> 3;
        const u64* wdU = (const u64*)sWdT;
#pragma unroll 1
        for (int e = 0; e < EPW; e++) {
            hid[lane]      = fmaxf(sum2(acc[e][0]) + sbf[lane],      0.f);
            hid[lane + 32] = fmaxf(sum2(acc[e][1]) + sbf[lane + 32], 0.f);
            hid[lane + 64] = fmaxf(sum2(acc[e][2]) + sbf[lane + 64], 0.f);
            hid[lane + 96] = fmaxf(sum2(acc[e][3]) + sbf[lane + 96], 0.f);
            __syncwarp();

            const u64* hU = (const u64*)hid;
            u64 p = 0;
#pragma unroll
            for (int hp = 0; hp < 16; hp++)
                p = fma2(hU[q * 16 + hp], wdU[(q * 16 + hp) * OUTD + o], p);
            float ps = sum2(p);
            ps += __shfl_down_sync(0xffffffffu, ps, 16);
            ps += __shfl_down_sync(0xffffffffu, ps, 8);
            if (lane < 8) out[(size_t)(b0 + e) * OUTD + lane] = ps + sbd[lane];
            __syncwarp();
        }
    }
}

extern "C" void kernel_launch(void* const* d_in, const int* in_sizes, int n_in,
                              void* d_out, int out_size)
{
    const float* obs = (const float*)d_in[0];
    const float* We  = (const float*)d_in[1];
    const float* be  = (const float*)d_in[2];
    const float* Wf  = (const float*)d_in[3];
    const float* bf  = (const float*)d_in[4];
    const float* Wd  = (const float*)d_in[5];
    const float* bd  = (const float*)d_in[6];
    float* out = (float*)d_out;

    const int B = in_sizes[0] / (NS * SS);
    const size_t smem = SMEM_FLOATS * sizeof(float);

    cudaFuncSetAttribute(gnn_kernel, cudaFuncAttributeMaxDynamicSharedMemorySize, (int)smem);

    const int blocks = 296;  // 2 per SM, persistent grid-stride
    gnn_kernel<<<blocks, THREADS, smem>>>(obs, We, be, Wf, bf, Wd, bd, out, B);
}